// round 1
// baseline (speedup 1.0000x reference)
#include <cuda_runtime.h>
#include <math.h>

// Problem constants
// B=2, L=2048, H=8, DK=DV=64, D=512, KSZ=3, pad=1
// rows of attention: B*H*L = 32768, eld matrix 16 x 2048 x 2048

#define NROWS 32768            // B*H*L
#define BH    16               // B*H
#define LSEQ  2048
#define DHEAD 64
#define DMOD  512
#define M4    4096             // B*L

// ---------------- device scratch (static; no runtime alloc allowed) -------
__device__ float g_qh[BH * LSEQ * DHEAD];       // [bh][l][dk]
__device__ float g_kh[BH * LSEQ * DHEAD];
__device__ float g_vh[BH * LSEQ * DHEAD];
__device__ float g_eld[(size_t)BH * LSEQ * LSEQ];   // 268MB logits
__device__ float g_attnout[M4 * DMOD];          // [b*l][h*64+dv]
__device__ float g_fcout[M4 * DMOD];
__device__ float g_dtab[4095];                  // float32(-alpha * d), d=-2047..2047

// ---------------- distance table (matches float64->float32 path of ref) ---
__global__ void k_dtab() {
    int t = blockIdx.x * blockDim.x + threadIdx.x;
    if (t < 4095) {
        double alpha = -log(0.001 / 7.0 * 3.0);   // ALPHA_C
        g_dtab[t] = (float)(-alpha * (double)(t - 2047));
    }
}

// ---------------- fused QKV projection: C = A[4096x512] * W^T[512x512] ----
// out scattered to [bh][l][dk] layout
__global__ void k_proj(const float* __restrict__ qi, const float* __restrict__ ki,
                       const float* __restrict__ vi, const float* __restrict__ wq,
                       const float* __restrict__ wk, const float* __restrict__ wv) {
    __shared__ __align__(16) float As[32][68];
    __shared__ __align__(16) float Ws[32][68];
    int z = blockIdx.z;
    const float* A = (z == 0) ? qi : (z == 1) ? ki : vi;
    const float* W = (z == 0) ? wq : (z == 1) ? wk : wv;
    float* O       = (z == 0) ? g_qh : (z == 1) ? g_kh : g_vh;

    int tid = threadIdx.x;
    int tx = tid & 15, ty = tid >> 4;
    int m0 = blockIdx.y * 64;
    int n0 = blockIdx.x * 64;

    float acc[4][4] = {};
    for (int kc = 0; kc < 512; kc += 32) {
#pragma unroll
        for (int p = 0; p < 2; p++) {
            int fid = tid + p * 256;
            int mm = fid >> 3;
            int k4 = (fid & 7) * 4;
            float4 av = *(const float4*)(A + (size_t)(m0 + mm) * 512 + kc + k4);
            As[k4 + 0][mm] = av.x; As[k4 + 1][mm] = av.y;
            As[k4 + 2][mm] = av.z; As[k4 + 3][mm] = av.w;
            float4 wv4 = *(const float4*)(W + (size_t)(n0 + mm) * 512 + kc + k4);
            Ws[k4 + 0][mm] = wv4.x; Ws[k4 + 1][mm] = wv4.y;
            Ws[k4 + 2][mm] = wv4.z; Ws[k4 + 3][mm] = wv4.w;
        }
        __syncthreads();
#pragma unroll
        for (int kk = 0; kk < 32; kk++) {
            float4 a = *(const float4*)&As[kk][ty * 4];
            float4 b = *(const float4*)&Ws[kk][tx * 4];
            float ar[4] = {a.x, a.y, a.z, a.w};
            float br[4] = {b.x, b.y, b.z, b.w};
#pragma unroll
            for (int mi = 0; mi < 4; mi++)
#pragma unroll
                for (int ni = 0; ni < 4; ni++)
                    acc[mi][ni] += ar[mi] * br[ni];
        }
        __syncthreads();
    }
    int n = n0 + tx * 4;
    int h = n >> 6, dk = n & 63;
#pragma unroll
    for (int mi = 0; mi < 4; mi++) {
        int m = m0 + ty * 4 + mi;
        int bb = m >> 11, l = m & 2047;
        float4 val = make_float4(acc[mi][0], acc[mi][1], acc[mi][2], acc[mi][3]);
        *(float4*)(O + ((size_t)(bb * 8 + h) * LSEQ + l) * 64 + dk) = val;
    }
}

// ---------------- eld logits: eld[i,j] = dtab[j-i] * (q_i . k_j / 8) ------
__global__ void k_eld() {
    __shared__ __align__(16) float Qs[64][68];
    __shared__ __align__(16) float Ks[64][68];
    int bh = blockIdx.z;
    int i0 = blockIdx.y * 64, j0 = blockIdx.x * 64;
    int tid = threadIdx.x;
    int tx = tid & 15, ty = tid >> 4;
    const float* Qp = g_qh + (size_t)bh * LSEQ * 64;
    const float* Kp = g_kh + (size_t)bh * LSEQ * 64;

#pragma unroll
    for (int p = 0; p < 4; p++) {
        int fid = tid + p * 256;
        int mm = fid >> 4;
        int k4 = (fid & 15) * 4;
        float4 qv = *(const float4*)(Qp + (size_t)(i0 + mm) * 64 + k4);
        Qs[k4 + 0][mm] = qv.x; Qs[k4 + 1][mm] = qv.y;
        Qs[k4 + 2][mm] = qv.z; Qs[k4 + 3][mm] = qv.w;
        float4 kv = *(const float4*)(Kp + (size_t)(j0 + mm) * 64 + k4);
        Ks[k4 + 0][mm] = kv.x; Ks[k4 + 1][mm] = kv.y;
        Ks[k4 + 2][mm] = kv.z; Ks[k4 + 3][mm] = kv.w;
    }
    __syncthreads();

    float acc[4][4] = {};
#pragma unroll
    for (int kk = 0; kk < 64; kk++) {
        float4 a = *(const float4*)&Qs[kk][ty * 4];
        float4 b = *(const float4*)&Ks[kk][tx * 4];
        float ar[4] = {a.x, a.y, a.z, a.w};
        float br[4] = {b.x, b.y, b.z, b.w};
#pragma unroll
        for (int mi = 0; mi < 4; mi++)
#pragma unroll
            for (int ni = 0; ni < 4; ni++)
                acc[mi][ni] += ar[mi] * br[ni];
    }

    int j = j0 + tx * 4;
#pragma unroll
    for (int mi = 0; mi < 4; mi++) {
        int i = i0 + ty * 4 + mi;
        int dbase = j - i + 2047;
        float e0 = g_dtab[dbase + 0] * (acc[mi][0] * 0.125f);
        float e1 = g_dtab[dbase + 1] * (acc[mi][1] * 0.125f);
        float e2 = g_dtab[dbase + 2] * (acc[mi][2] * 0.125f);
        float e3 = g_dtab[dbase + 3] * (acc[mi][3] * 0.125f);
        *(float4*)(g_eld + ((size_t)bh * LSEQ + i) * LSEQ + j) = make_float4(e0, e1, e2, e3);
    }
}

// ---------------- per-row softmax + avg-pool + sparse PV ------------------
// one block per attention row (b,h,i). 256 threads, 8 contiguous cols each.
__global__ void k_row(float* __restrict__ pooled_out) {
    __shared__ __align__(16) float p_sh[2048];       // normalized probs
    __shared__ __align__(16) float pooled_sh[2048];  // pooled probs
    __shared__ float red[256];
    __shared__ unsigned int mask_sh[64];

    int tid = threadIdx.x;
    int row = blockIdx.x;
    int bh = row >> 11;
    int i  = row & 2047;
    int b  = bh >> 3, h = bh & 7;

    const float* eldrow = g_eld + (size_t)row * LSEQ;
    int j0 = tid * 8;
    float4 v0 = *(const float4*)(eldrow + j0);
    float4 v1 = *(const float4*)(eldrow + j0 + 4);
    float e8[8] = {v0.x, v0.y, v0.z, v0.w, v1.x, v1.y, v1.z, v1.w};
    if (tid < 64) mask_sh[tid] = 0;

    // row max
    float m = e8[0];
#pragma unroll
    for (int u = 1; u < 8; u++) m = fmaxf(m, e8[u]);
    red[tid] = m;
    __syncthreads();
    for (int s = 128; s > 0; s >>= 1) {
        if (tid < s) red[tid] = fmaxf(red[tid], red[tid + s]);
        __syncthreads();
    }
    float mx = red[0];
    __syncthreads();

    // exp (only where it won't underflow to ~0) + sum
    float ev[8];
    float lsum = 0.f;
#pragma unroll
    for (int u = 0; u < 8; u++) {
        float arg = e8[u] - mx;
        float e = 0.f;
        if (arg > -88.0f) e = expf(arg);
        ev[u] = e;
        lsum += e;
    }
    red[tid] = lsum;
    __syncthreads();
    for (int s = 128; s > 0; s >>= 1) {
        if (tid < s) red[tid] = red[tid] + red[tid + s];
        __syncthreads();
    }
    float S = red[0];
    __syncthreads();

    // normalize (divide only nonzeros; correctly-rounded div to match ref)
#pragma unroll
    for (int u = 0; u < 8; u++)
        p_sh[j0 + u] = (ev[u] != 0.f) ? (ev[u] / S) : 0.f;
    __syncthreads();

    // avg_pool1d kernel=3 pad=1 count_include_pad : ((p[j-1]+p[j])+p[j+1])/3
    float pc[8];
    {
        float4 c0 = *(const float4*)(p_sh + j0);
        float4 c1 = *(const float4*)(p_sh + j0 + 4);
        pc[0] = c0.x; pc[1] = c0.y; pc[2] = c0.z; pc[3] = c0.w;
        pc[4] = c1.x; pc[5] = c1.y; pc[6] = c1.z; pc[7] = c1.w;
    }
    float pl = (tid == 0)   ? 0.f : p_sh[j0 - 1];
    float pr = (tid == 255) ? 0.f : p_sh[j0 + 8];

    float pv[8];
    unsigned int bits = 0;
#pragma unroll
    for (int u = 0; u < 8; u++) {
        float pm = (u == 0) ? pl : pc[u - 1];
        float pz = pc[u];
        float pp = (u == 7) ? pr : pc[u + 1];
        float out = 0.f;
        if (pm != 0.f || pz != 0.f || pp != 0.f) {
            out = ((pm + pz) + pp) / 3.0f;
            bits |= (1u << u);
        }
        pv[u] = out;
    }
    size_t prow = (size_t)row * LSEQ + j0;
    *(float4*)(pooled_out + prow)     = make_float4(pv[0], pv[1], pv[2], pv[3]);
    *(float4*)(pooled_out + prow + 4) = make_float4(pv[4], pv[5], pv[6], pv[7]);
#pragma unroll
    for (int u = 0; u < 8; u++) pooled_sh[j0 + u] = pv[u];
    if (bits) atomicOr(&mask_sh[tid >> 2], bits << ((tid & 3) * 8));
    __syncthreads();

    // sparse PV: out[dv] = sum_j pooled[j] * vh[j][dv], ascending j (deterministic)
    if (tid < 64) {
        int dv = tid;
        const float* vbase = g_vh + (size_t)bh * LSEQ * 64;
        float acc = 0.f;
#pragma unroll 1
        for (int w = 0; w < 64; w++) {
            unsigned int bw = mask_sh[w];
            while (bw) {
                int bp = __ffs((int)bw) - 1;
                bw &= (bw - 1);
                int j = w * 32 + bp;
                acc = fmaf(pooled_sh[j], vbase[(size_t)j * 64 + dv], acc);
            }
        }
        g_attnout[((size_t)(b * LSEQ + i)) * DMOD + h * 64 + dv] = acc;
    }
}

// ---------------- fc projection: fcout = attnout[4096x512] * w_fc^T -------
__global__ void k_fc(const float* __restrict__ wfc) {
    __shared__ __align__(16) float As[32][68];
    __shared__ __align__(16) float Ws[32][68];
    int tid = threadIdx.x;
    int tx = tid & 15, ty = tid >> 4;
    int m0 = blockIdx.y * 64;
    int n0 = blockIdx.x * 64;

    float acc[4][4] = {};
    for (int kc = 0; kc < 512; kc += 32) {
#pragma unroll
        for (int p = 0; p < 2; p++) {
            int fid = tid + p * 256;
            int mm = fid >> 3;
            int k4 = (fid & 7) * 4;
            float4 av = *(const float4*)(g_attnout + (size_t)(m0 + mm) * 512 + kc + k4);
            As[k4 + 0][mm] = av.x; As[k4 + 1][mm] = av.y;
            As[k4 + 2][mm] = av.z; As[k4 + 3][mm] = av.w;
            float4 wv4 = *(const float4*)(wfc + (size_t)(n0 + mm) * 512 + kc + k4);
            Ws[k4 + 0][mm] = wv4.x; Ws[k4 + 1][mm] = wv4.y;
            Ws[k4 + 2][mm] = wv4.z; Ws[k4 + 3][mm] = wv4.w;
        }
        __syncthreads();
#pragma unroll
        for (int kk = 0; kk < 32; kk++) {
            float4 a = *(const float4*)&As[kk][ty * 4];
            float4 b = *(const float4*)&Ws[kk][tx * 4];
            float ar[4] = {a.x, a.y, a.z, a.w};
            float br[4] = {b.x, b.y, b.z, b.w};
#pragma unroll
            for (int mi = 0; mi < 4; mi++)
#pragma unroll
                for (int ni = 0; ni < 4; ni++)
                    acc[mi][ni] += ar[mi] * br[ni];
        }
        __syncthreads();
    }
#pragma unroll
    for (int mi = 0; mi < 4; mi++) {
        int m = m0 + ty * 4 + mi;
        float4 val = make_float4(acc[mi][0], acc[mi][1], acc[mi][2], acc[mi][3]);
        *(float4*)(g_fcout + (size_t)m * 512 + n0 + tx * 4) = val;
    }
}

// ---------------- residual + LayerNorm ------------------------------------
__global__ void k_ln(const float* __restrict__ resid, const float* __restrict__ gamma,
                     const float* __restrict__ beta, float* __restrict__ outp) {
    __shared__ float red[128];
    int m = blockIdx.x;
    int tid = threadIdx.x;   // 128 threads * 4 elems
    float4 f = *(const float4*)(g_fcout + (size_t)m * 512 + tid * 4);
    float4 r = *(const float4*)(resid + (size_t)m * 512 + tid * 4);
    float y[4] = {f.x + r.x, f.y + r.y, f.z + r.z, f.w + r.w};

    float s = (y[0] + y[1]) + (y[2] + y[3]);
    red[tid] = s;
    __syncthreads();
    for (int st = 64; st > 0; st >>= 1) {
        if (tid < st) red[tid] += red[tid + st];
        __syncthreads();
    }
    float mu = red[0] * (1.0f / 512.0f);
    __syncthreads();

    float d[4] = {y[0] - mu, y[1] - mu, y[2] - mu, y[3] - mu};
    float sq = (d[0] * d[0] + d[1] * d[1]) + (d[2] * d[2] + d[3] * d[3]);
    red[tid] = sq;
    __syncthreads();
    for (int st = 64; st > 0; st >>= 1) {
        if (tid < st) red[tid] += red[tid + st];
        __syncthreads();
    }
    float var = red[0] * (1.0f / 512.0f);
    float inv = 1.0f / sqrtf(var + 1e-6f);

    float4 g = *(const float4*)(gamma + tid * 4);
    float4 bb = *(const float4*)(beta + tid * 4);
    float4 o = make_float4(d[0] * inv * g.x + bb.x, d[1] * inv * g.y + bb.y,
                           d[2] * inv * g.z + bb.z, d[3] * inv * g.w + bb.w);
    *(float4*)(outp + (size_t)m * 512 + tid * 4) = o;
}

// ---------------- launch ---------------------------------------------------
extern "C" void kernel_launch(void* const* d_in, const int* in_sizes, int n_in,
                              void* d_out, int out_size) {
    const float* q     = (const float*)d_in[0];
    const float* k     = (const float*)d_in[1];
    const float* v     = (const float*)d_in[2];
    const float* wq    = (const float*)d_in[3];
    const float* wk    = (const float*)d_in[4];
    const float* wv    = (const float*)d_in[5];
    const float* wfc   = (const float*)d_in[6];
    const float* gamma = (const float*)d_in[7];
    const float* beta  = (const float*)d_in[8];

    float* outp = (float*)d_out;            // [B,L,1,D] = 2,097,152 floats
    float* pooledp = outp + 2097152;        // [B,H,L,L] = 67,108,864 floats

    k_dtab<<<16, 256>>>();
    k_proj<<<dim3(8, 64, 3), 256>>>(q, k, v, wq, wk, wv);
    k_eld<<<dim3(32, 32, 16), 256>>>();
    k_row<<<32768, 256>>>(pooledp);
    k_fc<<<dim3(8, 64), 256>>>(wfc);
    k_ln<<<4096, 128>>>(q, gamma, beta, outp);
}

// round 2
// speedup vs baseline: 1.1512x; 1.1512x over previous
#include <cuda_runtime.h>
#include <math.h>

// B=2, L=2048, H=8, DK=DV=64, D=512, KSZ=3, pad=1
#define NROWS 32768            // B*H*L
#define BH    16               // B*H
#define LSEQ  2048
#define DHEAD 64
#define DMOD  512
#define M4    4096             // B*L

// ---------------- device scratch (static; no runtime alloc allowed) -------
__device__ float g_qh[BH * LSEQ * DHEAD];       // [bh][l][dk]
__device__ float g_kh[BH * LSEQ * DHEAD];
__device__ float g_vh[BH * LSEQ * DHEAD];
__device__ float g_eld[(size_t)BH * LSEQ * LSEQ];   // 268MB logits
__device__ float g_attnout[M4 * DMOD];          // [b*l][h*64+dv]
__device__ float g_fcout[M4 * DMOD];
__device__ float g_dtab[4095];                  // float32(-alpha * d), d=-2047..2047
__device__ unsigned int g_rowmax_u[NROWS];      // monotonic-uint encoded row maxima

// ---------------- init: distance table + rowmax identity ------------------
__global__ void k_init() {
    int t = blockIdx.x * blockDim.x + threadIdx.x;
    if (t < 4095) {
        double alpha = -log(0.001 / 7.0 * 3.0);   // ALPHA_C
        g_dtab[t] = (float)(-alpha * (double)(t - 2047));
    }
    if (t < NROWS) g_rowmax_u[t] = 0u;            // identity under encoded max
}

// ---------------- fused QKV projection: C = A[4096x512] * W^T[512x512] ----
__global__ void k_proj(const float* __restrict__ qi, const float* __restrict__ ki,
                       const float* __restrict__ vi, const float* __restrict__ wq,
                       const float* __restrict__ wk, const float* __restrict__ wv) {
    __shared__ __align__(16) float As[32][68];
    __shared__ __align__(16) float Ws[32][68];
    int z = blockIdx.z;
    const float* A = (z == 0) ? qi : (z == 1) ? ki : vi;
    const float* W = (z == 0) ? wq : (z == 1) ? wk : wv;
    float* O       = (z == 0) ? g_qh : (z == 1) ? g_kh : g_vh;

    int tid = threadIdx.x;
    int tx = tid & 15, ty = tid >> 4;
    int m0 = blockIdx.y * 64;
    int n0 = blockIdx.x * 64;

    float acc[4][4] = {};
    for (int kc = 0; kc < 512; kc += 32) {
#pragma unroll
        for (int p = 0; p < 2; p++) {
            int fid = tid + p * 256;
            int mm = fid >> 3;
            int k4 = (fid & 7) * 4;
            float4 av = *(const float4*)(A + (size_t)(m0 + mm) * 512 + kc + k4);
            As[k4 + 0][mm] = av.x; As[k4 + 1][mm] = av.y;
            As[k4 + 2][mm] = av.z; As[k4 + 3][mm] = av.w;
            float4 wv4 = *(const float4*)(W + (size_t)(n0 + mm) * 512 + kc + k4);
            Ws[k4 + 0][mm] = wv4.x; Ws[k4 + 1][mm] = wv4.y;
            Ws[k4 + 2][mm] = wv4.z; Ws[k4 + 3][mm] = wv4.w;
        }
        __syncthreads();
#pragma unroll
        for (int kk = 0; kk < 32; kk++) {
            float4 a = *(const float4*)&As[kk][ty * 4];
            float4 b = *(const float4*)&Ws[kk][tx * 4];
            float ar[4] = {a.x, a.y, a.z, a.w};
            float br[4] = {b.x, b.y, b.z, b.w};
#pragma unroll
            for (int mi = 0; mi < 4; mi++)
#pragma unroll
                for (int ni = 0; ni < 4; ni++)
                    acc[mi][ni] += ar[mi] * br[ni];
        }
        __syncthreads();
    }
    int n = n0 + tx * 4;
    int h = n >> 6, dk = n & 63;
#pragma unroll
    for (int mi = 0; mi < 4; mi++) {
        int m = m0 + ty * 4 + mi;
        int bb = m >> 11, l = m & 2047;
        float4 val = make_float4(acc[mi][0], acc[mi][1], acc[mi][2], acc[mi][3]);
        *(float4*)(O + ((size_t)(bb * 8 + h) * LSEQ + l) * 64 + dk) = val;
    }
}

// ---------------- eld logits + fused row-max atomics ----------------------
// eld[i,j] = dtab[j-i] * (q_i . k_j / 8); also atomicMax per-row maxima.
__global__ void k_eld() {
    __shared__ __align__(16) float Qs[64][68];
    __shared__ __align__(16) float Ks[64][68];
    int bh = blockIdx.z;
    int i0 = blockIdx.y * 64, j0 = blockIdx.x * 64;
    int tid = threadIdx.x;
    int tx = tid & 15, ty = tid >> 4;
    const float* Qp = g_qh + (size_t)bh * LSEQ * 64;
    const float* Kp = g_kh + (size_t)bh * LSEQ * 64;

#pragma unroll
    for (int p = 0; p < 4; p++) {
        int fid = tid + p * 256;
        int mm = fid >> 4;
        int k4 = (fid & 15) * 4;
        float4 qv = *(const float4*)(Qp + (size_t)(i0 + mm) * 64 + k4);
        Qs[k4 + 0][mm] = qv.x; Qs[k4 + 1][mm] = qv.y;
        Qs[k4 + 2][mm] = qv.z; Qs[k4 + 3][mm] = qv.w;
        float4 kv = *(const float4*)(Kp + (size_t)(j0 + mm) * 64 + k4);
        Ks[k4 + 0][mm] = kv.x; Ks[k4 + 1][mm] = kv.y;
        Ks[k4 + 2][mm] = kv.z; Ks[k4 + 3][mm] = kv.w;
    }
    __syncthreads();

    float acc[4][4] = {};
#pragma unroll
    for (int kk = 0; kk < 64; kk++) {
        float4 a = *(const float4*)&Qs[kk][ty * 4];
        float4 b = *(const float4*)&Ks[kk][tx * 4];
        float ar[4] = {a.x, a.y, a.z, a.w};
        float br[4] = {b.x, b.y, b.z, b.w};
#pragma unroll
        for (int mi = 0; mi < 4; mi++)
#pragma unroll
            for (int ni = 0; ni < 4; ni++)
                acc[mi][ni] += ar[mi] * br[ni];
    }

    int j = j0 + tx * 4;
    float rmx[4];
#pragma unroll
    for (int mi = 0; mi < 4; mi++) {
        int i = i0 + ty * 4 + mi;
        int dbase = j - i + 2047;
        float e0 = g_dtab[dbase + 0] * (acc[mi][0] * 0.125f);
        float e1 = g_dtab[dbase + 1] * (acc[mi][1] * 0.125f);
        float e2 = g_dtab[dbase + 2] * (acc[mi][2] * 0.125f);
        float e3 = g_dtab[dbase + 3] * (acc[mi][3] * 0.125f);
        *(float4*)(g_eld + ((size_t)bh * LSEQ + i) * LSEQ + j) = make_float4(e0, e1, e2, e3);
        rmx[mi] = fmaxf(fmaxf(e0, e1), fmaxf(e2, e3));
    }
    // reduce over tx (lanes 0-15 / 16-31 are distinct ty; xor<16 stays in half)
#pragma unroll
    for (int mi = 0; mi < 4; mi++) {
        float r = rmx[mi];
#pragma unroll
        for (int o = 1; o < 16; o <<= 1)
            r = fmaxf(r, __shfl_xor_sync(0xffffffffu, r, o));
        if (tx == 0) {
            int i = i0 + ty * 4 + mi;
            unsigned int u = __float_as_uint(r);
            unsigned int key = (u & 0x80000000u) ? ~u : (u | 0x80000000u);
            atomicMax(&g_rowmax_u[bh * LSEQ + i], key);
        }
    }
}

// ---------------- sparse softmax + pool + PV (max precomputed) ------------
__global__ void k_row2(float* __restrict__ pooled_out) {
    __shared__ __align__(16) float p_sh[2048];
    __shared__ unsigned int mask_sh[64];
    __shared__ float redS[8];

    int tid = threadIdx.x;
    int row = blockIdx.x;
    int bh = row >> 11;
    int i  = row & 2047;
    int b  = bh >> 3, h = bh & 7;

    // zero prob array + candidate mask
    ((float4*)p_sh)[tid * 2]     = make_float4(0.f, 0.f, 0.f, 0.f);
    ((float4*)p_sh)[tid * 2 + 1] = make_float4(0.f, 0.f, 0.f, 0.f);
    if (tid < 64) mask_sh[tid] = 0u;

    // decode precomputed row max
    unsigned int kk = g_rowmax_u[row];
    unsigned int ub = (kk & 0x80000000u) ? (kk ^ 0x80000000u) : ~kk;
    float mx = __uint_as_float(ub);

    const float* eldrow = g_eld + (size_t)row * LSEQ;
    int j0 = tid * 8;
    float4 v0 = *(const float4*)(eldrow + j0);
    float4 v1 = *(const float4*)(eldrow + j0 + 4);
    float e8[8] = {v0.x, v0.y, v0.z, v0.w, v1.x, v1.y, v1.z, v1.w};

    float ev[8];
    float lsum = 0.f;
#pragma unroll
    for (int u = 0; u < 8; u++) {
        float arg = e8[u] - mx;
        float e = 0.f;
        if (arg > -88.0f) e = expf(arg);
        ev[u] = e;
        lsum += e;
    }
    // block sum of exps
#pragma unroll
    for (int o = 16; o > 0; o >>= 1)
        lsum += __shfl_xor_sync(0xffffffffu, lsum, o);
    if ((tid & 31) == 0) redS[tid >> 5] = lsum;
    __syncthreads();   // also orders the zero-fills above
    float S = ((redS[0] + redS[1]) + (redS[2] + redS[3])) +
              ((redS[4] + redS[5]) + (redS[6] + redS[7]));

    // scatter sparse probs + candidate bits (j-1, j, j+1)
    unsigned int bits = 0;
#pragma unroll
    for (int u = 0; u < 8; u++) {
        if (ev[u] != 0.f) { p_sh[j0 + u] = ev[u] / S; bits |= (1u << u); }
    }
    if (bits) {
#pragma unroll
        for (int u = 0; u < 8; u++) {
            if (bits & (1u << u)) {
                int jj = j0 + u;
                int lo = (jj > 0) ? jj - 1 : 0;
                int hi = (jj < 2047) ? jj + 1 : 2047;
                for (int pp = lo; pp <= hi; pp++)
                    atomicOr(&mask_sh[pp >> 5], 1u << (pp & 31));
            }
        }
    }
    __syncthreads();

    // pooled output: zeros except candidate positions
    unsigned int wmask = mask_sh[tid >> 2];
    unsigned int myb = (wmask >> ((tid & 3) * 8)) & 0xffu;
    float pv[8] = {0.f, 0.f, 0.f, 0.f, 0.f, 0.f, 0.f, 0.f};
    if (myb) {
#pragma unroll
        for (int u = 0; u < 8; u++) {
            if (myb & (1u << u)) {
                int pos = j0 + u;
                float pm = (pos > 0)    ? p_sh[pos - 1] : 0.f;
                float pz = p_sh[pos];
                float pq = (pos < 2047) ? p_sh[pos + 1] : 0.f;
                pv[u] = ((pm + pz) + pq) / 3.0f;
            }
        }
    }
    size_t prow = (size_t)row * LSEQ + j0;
    *(float4*)(pooled_out + prow)     = make_float4(pv[0], pv[1], pv[2], pv[3]);
    *(float4*)(pooled_out + prow + 4) = make_float4(pv[4], pv[5], pv[6], pv[7]);

    // sparse PV over candidate positions (ascending -> deterministic)
    if (tid < 64) {
        const float* vbase = g_vh + (size_t)bh * LSEQ * 64 + tid;
        float acc = 0.f;
#pragma unroll 1
        for (int w = 0; w < 64; w++) {
            unsigned int bw = mask_sh[w];
            while (bw) {
                int bp = __ffs((int)bw) - 1;
                bw &= (bw - 1);
                int pos = w * 32 + bp;
                float pm = (pos > 0)    ? p_sh[pos - 1] : 0.f;
                float pz = p_sh[pos];
                float pq = (pos < 2047) ? p_sh[pos + 1] : 0.f;
                float val = ((pm + pz) + pq) / 3.0f;
                acc = fmaf(val, vbase[(size_t)pos * 64], acc);
            }
        }
        g_attnout[((size_t)(b * LSEQ + i)) * DMOD + h * 64 + tid] = acc;
    }
}

// ---------------- fc projection: fcout = attnout[4096x512] * w_fc^T -------
__global__ void k_fc(const float* __restrict__ wfc) {
    __shared__ __align__(16) float As[32][68];
    __shared__ __align__(16) float Ws[32][68];
    int tid = threadIdx.x;
    int tx = tid & 15, ty = tid >> 4;
    int m0 = blockIdx.y * 64;
    int n0 = blockIdx.x * 64;

    float acc[4][4] = {};
    for (int kc = 0; kc < 512; kc += 32) {
#pragma unroll
        for (int p = 0; p < 2; p++) {
            int fid = tid + p * 256;
            int mm = fid >> 3;
            int k4 = (fid & 7) * 4;
            float4 av = *(const float4*)(g_attnout + (size_t)(m0 + mm) * 512 + kc + k4);
            As[k4 + 0][mm] = av.x; As[k4 + 1][mm] = av.y;
            As[k4 + 2][mm] = av.z; As[k4 + 3][mm] = av.w;
            float4 wv4 = *(const float4*)(wfc + (size_t)(n0 + mm) * 512 + kc + k4);
            Ws[k4 + 0][mm] = wv4.x; Ws[k4 + 1][mm] = wv4.y;
            Ws[k4 + 2][mm] = wv4.z; Ws[k4 + 3][mm] = wv4.w;
        }
        __syncthreads();
#pragma unroll
        for (int kk = 0; kk < 32; kk++) {
            float4 a = *(const float4*)&As[kk][ty * 4];
            float4 b = *(const float4*)&Ws[kk][tx * 4];
            float ar[4] = {a.x, a.y, a.z, a.w};
            float br[4] = {b.x, b.y, b.z, b.w};
#pragma unroll
            for (int mi = 0; mi < 4; mi++)
#pragma unroll
                for (int ni = 0; ni < 4; ni++)
                    acc[mi][ni] += ar[mi] * br[ni];
        }
        __syncthreads();
    }
#pragma unroll
    for (int mi = 0; mi < 4; mi++) {
        int m = m0 + ty * 4 + mi;
        float4 val = make_float4(acc[mi][0], acc[mi][1], acc[mi][2], acc[mi][3]);
        *(float4*)(g_fcout + (size_t)m * 512 + n0 + tx * 4) = val;
    }
}

// ---------------- residual + LayerNorm ------------------------------------
__global__ void k_ln(const float* __restrict__ resid, const float* __restrict__ gamma,
                     const float* __restrict__ beta, float* __restrict__ outp) {
    __shared__ float red[128];
    int m = blockIdx.x;
    int tid = threadIdx.x;
    float4 f = *(const float4*)(g_fcout + (size_t)m * 512 + tid * 4);
    float4 r = *(const float4*)(resid + (size_t)m * 512 + tid * 4);
    float y[4] = {f.x + r.x, f.y + r.y, f.z + r.z, f.w + r.w};

    float s = (y[0] + y[1]) + (y[2] + y[3]);
    red[tid] = s;
    __syncthreads();
    for (int st = 64; st > 0; st >>= 1) {
        if (tid < st) red[tid] += red[tid + st];
        __syncthreads();
    }
    float mu = red[0] * (1.0f / 512.0f);
    __syncthreads();

    float d[4] = {y[0] - mu, y[1] - mu, y[2] - mu, y[3] - mu};
    float sq = (d[0] * d[0] + d[1] * d[1]) + (d[2] * d[2] + d[3] * d[3]);
    red[tid] = sq;
    __syncthreads();
    for (int st = 64; st > 0; st >>= 1) {
        if (tid < st) red[tid] += red[tid + st];
        __syncthreads();
    }
    float var = red[0] * (1.0f / 512.0f);
    float inv = 1.0f / sqrtf(var + 1e-6f);

    float4 g = *(const float4*)(gamma + tid * 4);
    float4 bb = *(const float4*)(beta + tid * 4);
    float4 o = make_float4(d[0] * inv * g.x + bb.x, d[1] * inv * g.y + bb.y,
                           d[2] * inv * g.z + bb.z, d[3] * inv * g.w + bb.w);
    *(float4*)(outp + (size_t)m * 512 + tid * 4) = o;
}

// ---------------- launch ---------------------------------------------------
extern "C" void kernel_launch(void* const* d_in, const int* in_sizes, int n_in,
                              void* d_out, int out_size) {
    const float* q     = (const float*)d_in[0];
    const float* k     = (const float*)d_in[1];
    const float* v     = (const float*)d_in[2];
    const float* wq    = (const float*)d_in[3];
    const float* wk    = (const float*)d_in[4];
    const float* wv    = (const float*)d_in[5];
    const float* wfc   = (const float*)d_in[6];
    const float* gamma = (const float*)d_in[7];
    const float* beta  = (const float*)d_in[8];

    float* outp = (float*)d_out;            // [B,L,1,D]
    float* pooledp = outp + 2097152;        // [B,H,L,L]

    k_init<<<128, 256>>>();
    k_proj<<<dim3(8, 64, 3), 256>>>(q, k, v, wq, wk, wv);
    k_eld<<<dim3(32, 32, 16), 256>>>();
    k_row2<<<32768, 256>>>(pooledp);
    k_fc<<<dim3(8, 64), 256>>>(wfc);
    k_ln<<<4096, 128>>>(q, gamma, beta, outp);
}

// round 4
// speedup vs baseline: 1.2530x; 1.0884x over previous
#include <cuda_runtime.h>
#include <cuda_bf16.h>
#include <math.h>

// B=2, L=2048, H=8, DK=DV=64, D=512, KSZ=3, pad=1
#define NROWS 32768            // B*H*L
#define BH    16               // B*H
#define LSEQ  2048
#define DHEAD 64
#define DMOD  512
#define M4    4096             // B*L

// ---------------- device scratch -------------------------------------------
__device__ float g_vh[BH * LSEQ * DHEAD];
__device__ __align__(128) __nv_bfloat16 g_qs[3][BH * LSEQ * DHEAD];   // bf16x3 splits of qh
__device__ __align__(128) __nv_bfloat16 g_ks[3][BH * LSEQ * DHEAD];   // bf16x3 splits of kh
__device__ float g_eld[(size_t)BH * LSEQ * LSEQ];   // 268MB logits
__device__ float g_attnout[M4 * DMOD];
__device__ float g_fcout[M4 * DMOD];
__device__ float g_dtab[4095];
__device__ unsigned int g_rowmax_u[NROWS];

// ---------------- helpers ----------------------------------------------------
__device__ __forceinline__ unsigned smem_u32(const void* p) {
    unsigned a;
    asm("{ .reg .u64 t; cvta.to.shared.u64 t, %1; cvt.u32.u64 %0, t; }" : "=r"(a) : "l"(p));
    return a;
}
__device__ __forceinline__ unsigned sw128(unsigned x) { return x ^ ((x >> 3) & 0x70); }

#define LDSM_X4(r0, r1, r2, r3, addr) \
    asm volatile("ldmatrix.sync.aligned.m8n8.x4.shared.b16 {%0,%1,%2,%3}, [%4];" \
                 : "=r"(r0), "=r"(r1), "=r"(r2), "=r"(r3) : "r"(addr))

#define MMA16816(d, a, b) \
    asm volatile("mma.sync.aligned.m16n8k16.row.col.f32.bf16.bf16.f32 " \
                 "{%0,%1,%2,%3}, {%4,%5,%6,%7}, {%8,%9}, {%0,%1,%2,%3};" \
                 : "+f"((d)[0]), "+f"((d)[1]), "+f"((d)[2]), "+f"((d)[3]) \
                 : "r"((a)[0]), "r"((a)[1]), "r"((a)[2]), "r"((a)[3]), \
                   "r"((b)[0]), "r"((b)[1]))

// ---------------- init ------------------------------------------------------
__global__ void k_init() {
    int t = blockIdx.x * blockDim.x + threadIdx.x;
    if (t < 4095) {
        double alpha = -log(0.001 / 7.0 * 3.0);   // ALPHA_C
        g_dtab[t] = (float)(-alpha * (double)(t - 2047));
    }
    if (t < NROWS) g_rowmax_u[t] = 0u;
}

// ---------------- fused QKV projection --------------------------------------
// q,k outputs written as bf16x3 splits; v output fp32.
__global__ void k_proj(const float* __restrict__ qi, const float* __restrict__ ki,
                       const float* __restrict__ vi, const float* __restrict__ wq,
                       const float* __restrict__ wk, const float* __restrict__ wv) {
    __shared__ __align__(16) float As[32][68];
    __shared__ __align__(16) float Ws[32][68];
    int z = blockIdx.z;
    const float* A = (z == 0) ? qi : (z == 1) ? ki : vi;
    const float* W = (z == 0) ? wq : (z == 1) ? wk : wv;

    int tid = threadIdx.x;
    int tx = tid & 15, ty = tid >> 4;
    int m0 = blockIdx.y * 64;
    int n0 = blockIdx.x * 64;

    float acc[4][4] = {};
    for (int kc = 0; kc < 512; kc += 32) {
#pragma unroll
        for (int p = 0; p < 2; p++) {
            int fid = tid + p * 256;
            int mm = fid >> 3;
            int k4 = (fid & 7) * 4;
            float4 av = *(const float4*)(A + (size_t)(m0 + mm) * 512 + kc + k4);
            As[k4 + 0][mm] = av.x; As[k4 + 1][mm] = av.y;
            As[k4 + 2][mm] = av.z; As[k4 + 3][mm] = av.w;
            float4 wv4 = *(const float4*)(W + (size_t)(n0 + mm) * 512 + kc + k4);
            Ws[k4 + 0][mm] = wv4.x; Ws[k4 + 1][mm] = wv4.y;
            Ws[k4 + 2][mm] = wv4.z; Ws[k4 + 3][mm] = wv4.w;
        }
        __syncthreads();
#pragma unroll
        for (int kk = 0; kk < 32; kk++) {
            float4 a = *(const float4*)&As[kk][ty * 4];
            float4 b = *(const float4*)&Ws[kk][tx * 4];
            float ar[4] = {a.x, a.y, a.z, a.w};
            float br[4] = {b.x, b.y, b.z, b.w};
#pragma unroll
            for (int mi = 0; mi < 4; mi++)
#pragma unroll
                for (int ni = 0; ni < 4; ni++)
                    acc[mi][ni] += ar[mi] * br[ni];
        }
        __syncthreads();
    }
    int n = n0 + tx * 4;
    int h = n >> 6, dk = n & 63;
#pragma unroll
    for (int mi = 0; mi < 4; mi++) {
        int m = m0 + ty * 4 + mi;
        int bb = m >> 11, l = m & 2047;
        size_t off = ((size_t)(bb * 8 + h) * LSEQ + l) * 64 + dk;
        if (z == 2) {
            *(float4*)(g_vh + off) =
                make_float4(acc[mi][0], acc[mi][1], acc[mi][2], acc[mi][3]);
        } else {
            __nv_bfloat16* S0 = (z == 0) ? g_qs[0] : g_ks[0];
            __nv_bfloat16* S1 = (z == 0) ? g_qs[1] : g_ks[1];
            __nv_bfloat16* S2 = (z == 0) ? g_qs[2] : g_ks[2];
            union { __nv_bfloat16 h4[4]; uint2 u; } p0, p1, p2;
#pragma unroll
            for (int u = 0; u < 4; u++) {
                float x = acc[mi][u];
                __nv_bfloat16 b0 = __float2bfloat16(x);
                float r = x - __bfloat162float(b0);
                __nv_bfloat16 b1 = __float2bfloat16(r);
                float r2 = r - __bfloat162float(b1);
                __nv_bfloat16 b2 = __float2bfloat16(r2);
                p0.h4[u] = b0; p1.h4[u] = b1; p2.h4[u] = b2;
            }
            *(uint2*)(S0 + off) = p0.u;
            *(uint2*)(S1 + off) = p1.u;
            *(uint2*)(S2 + off) = p2.u;
        }
    }
}

// ---------------- eld logits: HMMA bf16x3 emulated-fp32 GEMM ----------------
// 128x128 tile per CTA, 8 warps (4 M x 2 N), warp tile 32x64.
// D = sum of 6 split products; epilogue applies dtab*0.125, stages in smem,
// coalesced eld store + rowmax atomics.
extern __shared__ char eld_smem[];
__global__ void __launch_bounds__(256, 2) k_eld_mma() {
    int tid = threadIdx.x;
    int wid = tid >> 5, lane = tid & 31;
    int bh = blockIdx.z;
    int i0 = blockIdx.y * 128, j0 = blockIdx.x * 128;

    unsigned raw = smem_u32(eld_smem);
    unsigned sb = (raw + 1023) & ~1023u;
    char* smp = eld_smem + (sb - raw);

    // load 6 split tiles (A: q rows i0.., B: k rows j0..), SW128, 128B rows
    size_t rbq = ((size_t)bh * LSEQ + i0) * 64;
    size_t rbk = ((size_t)bh * LSEQ + j0) * 64;
#pragma unroll
    for (int s = 0; s < 3; s++) {
        const char* qsrc = (const char*)(g_qs[s] + rbq);
        const char* ksrc = (const char*)(g_ks[s] + rbk);
#pragma unroll
        for (int p = 0; p < 4; p++) {
            int f = tid + p * 256;
            int r = f >> 3;
            int cb = (f & 7) * 16;
            unsigned off = sw128(r * 128 + cb);
            *(uint4*)(smp + s * 16384 + off) = *(const uint4*)(qsrc + r * 128 + cb);
            *(uint4*)(smp + 49152 + s * 16384 + off) = *(const uint4*)(ksrc + r * 128 + cb);
        }
    }
    __syncthreads();

    int wr = wid & 3;          // M chunk: rows wr*32 .. +31
    int wc = wid >> 2;         // N chunk: cols wc*64 .. +63
    int sub = lane >> 3;       // ldmatrix lane-group
    int l7 = lane & 7;

    float acc[2][8][4];
#pragma unroll
    for (int mi = 0; mi < 2; mi++)
#pragma unroll
        for (int ni = 0; ni < 8; ni++)
#pragma unroll
            for (int u = 0; u < 4; u++) acc[mi][ni][u] = 0.f;

    const int pa[6] = {0, 0, 1, 1, 0, 2};
    const int pb[6] = {0, 1, 0, 1, 2, 0};
#pragma unroll
    for (int pr = 0; pr < 6; pr++) {
        unsigned abase = sb + pa[pr] * 16384;
        unsigned bbase = sb + 49152 + pb[pr] * 16384;
#pragma unroll
        for (int ks = 0; ks < 4; ks++) {
            int kb = ks * 32;
            // A fragments: mi tiles (16 rows each)
            unsigned afr[2][4];
#pragma unroll
            for (int mi = 0; mi < 2; mi++) {
                int r = wr * 32 + mi * 16 + l7 + (sub & 1) * 8;
                int byt = kb + (sub >> 1) * 16;
                unsigned ad = abase + sw128((unsigned)(r * 128 + byt));
                LDSM_X4(afr[mi][0], afr[mi][1], afr[mi][2], afr[mi][3], ad);
            }
            // B fragments: np pairs (16 n-rows each)
            unsigned bfr[8][2];
#pragma unroll
            for (int np = 0; np < 4; np++) {
                int n = wc * 64 + np * 16 + l7 + (sub >> 1) * 8;
                int byt = kb + (sub & 1) * 16;
                unsigned bd = bbase + sw128((unsigned)(n * 128 + byt));
                unsigned r0, r1, r2, r3;
                LDSM_X4(r0, r1, r2, r3, bd);
                bfr[np * 2][0] = r0; bfr[np * 2][1] = r1;
                bfr[np * 2 + 1][0] = r2; bfr[np * 2 + 1][1] = r3;
            }
#pragma unroll
            for (int mi = 0; mi < 2; mi++)
#pragma unroll
                for (int ni = 0; ni < 8; ni++)
                    MMA16816(acc[mi][ni], afr[mi], bfr[ni]);
        }
    }
    __syncthreads();   // done reading tiles; reuse smem as stage

    // epilogue: transform + stage + rowmax
    float* stage = (float*)smp;          // 128 x 132 floats
    int rbase = wr * 32 + (lane >> 2);
    int cbase = wc * 64 + (lane & 3) * 2;
    float mx[2][2] = {{-INFINITY, -INFINITY}, {-INFINITY, -INFINITY}};
#pragma unroll
    for (int mi = 0; mi < 2; mi++) {
#pragma unroll
        for (int ni = 0; ni < 8; ni++) {
#pragma unroll
            for (int u = 0; u < 4; u++) {
                int rloc = rbase + mi * 16 + (u >> 1) * 8;
                int cloc = cbase + ni * 8 + (u & 1);
                int i = i0 + rloc, j = j0 + cloc;
                float e = g_dtab[j - i + 2047] * (acc[mi][ni][u] * 0.125f);
                stage[rloc * 132 + cloc] = e;
                mx[mi][u >> 1] = fmaxf(mx[mi][u >> 1], e);
            }
        }
    }
    // per-row max: lanes sharing a row differ in (lane&3) -> xor 1,2
#pragma unroll
    for (int mi = 0; mi < 2; mi++)
#pragma unroll
        for (int hh = 0; hh < 2; hh++) {
            float r = mx[mi][hh];
            r = fmaxf(r, __shfl_xor_sync(0xffffffffu, r, 1));
            r = fmaxf(r, __shfl_xor_sync(0xffffffffu, r, 2));
            if ((lane & 3) == 0) {
                int i = i0 + rbase + mi * 16 + hh * 8;
                unsigned u = __float_as_uint(r);
                unsigned key = (u & 0x80000000u) ? ~u : (u | 0x80000000u);
                atomicMax(&g_rowmax_u[bh * LSEQ + i], key);
            }
        }
    __syncthreads();

    // coalesced store of the 128x128 tile
    float* erow = g_eld + ((size_t)bh * LSEQ + i0) * LSEQ + j0;
#pragma unroll
    for (int p = 0; p < 16; p++) {
        int f = tid + p * 256;           // 0..4095 float4s
        int r = f >> 5, q = f & 31;
        float4 v = *(const float4*)(stage + r * 132 + q * 4);
        *(float4*)(erow + (size_t)r * LSEQ + q * 4) = v;
    }
}

// ---------------- sparse softmax + pool + PV --------------------------------
__global__ void k_row2(float* __restrict__ pooled_out) {
    __shared__ __align__(16) float p_sh[2048];
    __shared__ unsigned int mask_sh[64];
    __shared__ float redS[8];

    int tid = threadIdx.x;
    int row = blockIdx.x;
    int bh = row >> 11;
    int i  = row & 2047;
    int b  = bh >> 3, h = bh & 7;

    ((float4*)p_sh)[tid * 2]     = make_float4(0.f, 0.f, 0.f, 0.f);
    ((float4*)p_sh)[tid * 2 + 1] = make_float4(0.f, 0.f, 0.f, 0.f);
    if (tid < 64) mask_sh[tid] = 0u;

    unsigned int kk = g_rowmax_u[row];
    unsigned int ub = (kk & 0x80000000u) ? (kk ^ 0x80000000u) : ~kk;
    float mx = __uint_as_float(ub);

    const float* eldrow = g_eld + (size_t)row * LSEQ;
    int j0 = tid * 8;
    float4 v0 = *(const float4*)(eldrow + j0);
    float4 v1 = *(const float4*)(eldrow + j0 + 4);
    float e8[8] = {v0.x, v0.y, v0.z, v0.w, v1.x, v1.y, v1.z, v1.w};

    float ev[8];
    float lsum = 0.f;
#pragma unroll
    for (int u = 0; u < 8; u++) {
        float arg = e8[u] - mx;
        float e = 0.f;
        if (arg > -88.0f) e = expf(arg);
        ev[u] = e;
        lsum += e;
    }
#pragma unroll
    for (int o = 16; o > 0; o >>= 1)
        lsum += __shfl_xor_sync(0xffffffffu, lsum, o);
    if ((tid & 31) == 0) redS[tid >> 5] = lsum;
    __syncthreads();
    float S = ((redS[0] + redS[1]) + (redS[2] + redS[3])) +
              ((redS[4] + redS[5]) + (redS[6] + redS[7]));

    unsigned int bits = 0;
#pragma unroll
    for (int u = 0; u < 8; u++) {
        if (ev[u] != 0.f) { p_sh[j0 + u] = ev[u] / S; bits |= (1u << u); }
    }
    if (bits) {
#pragma unroll
        for (int u = 0; u < 8; u++) {
            if (bits & (1u << u)) {
                int jj = j0 + u;
                int lo = (jj > 0) ? jj - 1 : 0;
                int hi = (jj < 2047) ? jj + 1 : 2047;
                for (int pp = lo; pp <= hi; pp++)
                    atomicOr(&mask_sh[pp >> 5], 1u << (pp & 31));
            }
        }
    }
    __syncthreads();

    unsigned int wmask = mask_sh[tid >> 2];
    unsigned int myb = (wmask >> ((tid & 3) * 8)) & 0xffu;
    float pv[8] = {0.f, 0.f, 0.f, 0.f, 0.f, 0.f, 0.f, 0.f};
    if (myb) {
#pragma unroll
        for (int u = 0; u < 8; u++) {
            if (myb & (1u << u)) {
                int pos = j0 + u;
                float pm = (pos > 0)    ? p_sh[pos - 1] : 0.f;
                float pz = p_sh[pos];
                float pq = (pos < 2047) ? p_sh[pos + 1] : 0.f;
                pv[u] = ((pm + pz) + pq) / 3.0f;
            }
        }
    }
    size_t prow = (size_t)row * LSEQ + j0;
    *(float4*)(pooled_out + prow)     = make_float4(pv[0], pv[1], pv[2], pv[3]);
    *(float4*)(pooled_out + prow + 4) = make_float4(pv[4], pv[5], pv[6], pv[7]);

    if (tid < 64) {
        const float* vbase = g_vh + (size_t)bh * LSEQ * 64 + tid;
        float acc = 0.f;
#pragma unroll 1
        for (int w = 0; w < 64; w++) {
            unsigned int bw = mask_sh[w];
            while (bw) {
                int bp = __ffs((int)bw) - 1;
                bw &= (bw - 1);
                int pos = w * 32 + bp;
                float pm = (pos > 0)    ? p_sh[pos - 1] : 0.f;
                float pz = p_sh[pos];
                float pq = (pos < 2047) ? p_sh[pos + 1] : 0.f;
                float val = ((pm + pz) + pq) / 3.0f;
                acc = fmaf(val, vbase[(size_t)pos * 64], acc);
            }
        }
        g_attnout[((size_t)(b * LSEQ + i)) * DMOD + h * 64 + tid] = acc;
    }
}

// ---------------- fc projection ---------------------------------------------
__global__ void k_fc(const float* __restrict__ wfc) {
    __shared__ __align__(16) float As[32][68];
    __shared__ __align__(16) float Ws[32][68];
    int tid = threadIdx.x;
    int tx = tid & 15, ty = tid >> 4;
    int m0 = blockIdx.y * 64;
    int n0 = blockIdx.x * 64;

    float acc[4][4] = {};
    for (int kc = 0; kc < 512; kc += 32) {
#pragma unroll
        for (int p = 0; p < 2; p++) {
            int fid = tid + p * 256;
            int mm = fid >> 3;
            int k4 = (fid & 7) * 4;
            float4 av = *(const float4*)(g_attnout + (size_t)(m0 + mm) * 512 + kc + k4);
            As[k4 + 0][mm] = av.x; As[k4 + 1][mm] = av.y;
            As[k4 + 2][mm] = av.z; As[k4 + 3][mm] = av.w;
            float4 wv4 = *(const float4*)(wfc + (size_t)(n0 + mm) * 512 + kc + k4);
            Ws[k4 + 0][mm] = wv4.x; Ws[k4 + 1][mm] = wv4.y;
            Ws[k4 + 2][mm] = wv4.z; Ws[k4 + 3][mm] = wv4.w;
        }
        __syncthreads();
#pragma unroll
        for (int kk = 0; kk < 32; kk++) {
            float4 a = *(const float4*)&As[kk][ty * 4];
            float4 b = *(const float4*)&Ws[kk][tx * 4];
            float ar[4] = {a.x, a.y, a.z, a.w};
            float br[4] = {b.x, b.y, b.z, b.w};
#pragma unroll
            for (int mi = 0; mi < 4; mi++)
#pragma unroll
                for (int ni = 0; ni < 4; ni++)
                    acc[mi][ni] += ar[mi] * br[ni];
        }
        __syncthreads();
    }
#pragma unroll
    for (int mi = 0; mi < 4; mi++) {
        int m = m0 + ty * 4 + mi;
        float4 val = make_float4(acc[mi][0], acc[mi][1], acc[mi][2], acc[mi][3]);
        *(float4*)(g_fcout + (size_t)m * 512 + n0 + tx * 4) = val;
    }
}

// ---------------- residual + LayerNorm --------------------------------------
__global__ void k_ln(const float* __restrict__ resid, const float* __restrict__ gamma,
                     const float* __restrict__ beta, float* __restrict__ outp) {
    __shared__ float red[128];
    int m = blockIdx.x;
    int tid = threadIdx.x;
    float4 f = *(const float4*)(g_fcout + (size_t)m * 512 + tid * 4);
    float4 r = *(const float4*)(resid + (size_t)m * 512 + tid * 4);
    float y[4] = {f.x + r.x, f.y + r.y, f.z + r.z, f.w + r.w};

    float s = (y[0] + y[1]) + (y[2] + y[3]);
    red[tid] = s;
    __syncthreads();
    for (int st = 64; st > 0; st >>= 1) {
        if (tid < st) red[tid] += red[tid + st];
        __syncthreads();
    }
    float mu = red[0] * (1.0f / 512.0f);
    __syncthreads();

    float d[4] = {y[0] - mu, y[1] - mu, y[2] - mu, y[3] - mu};
    float sq = (d[0] * d[0] + d[1] * d[1]) + (d[2] * d[2] + d[3] * d[3]);
    red[tid] = sq;
    __syncthreads();
    for (int st = 64; st > 0; st >>= 1) {
        if (tid < st) red[tid] += red[tid + st];
        __syncthreads();
    }
    float var = red[0] * (1.0f / 512.0f);
    float inv = 1.0f / sqrtf(var + 1e-6f);

    float4 g = *(const float4*)(gamma + tid * 4);
    float4 bb = *(const float4*)(beta + tid * 4);
    float4 o = make_float4(d[0] * inv * g.x + bb.x, d[1] * inv * g.y + bb.y,
                           d[2] * inv * g.z + bb.z, d[3] * inv * g.w + bb.w);
    *(float4*)(outp + (size_t)m * 512 + tid * 4) = o;
}

// ---------------- launch -----------------------------------------------------
#define ELD_SMEM (98304 + 1024)

extern "C" void kernel_launch(void* const* d_in, const int* in_sizes, int n_in,
                              void* d_out, int out_size) {
    const float* q     = (const float*)d_in[0];
    const float* k     = (const float*)d_in[1];
    const float* v     = (const float*)d_in[2];
    const float* wq    = (const float*)d_in[3];
    const float* wk    = (const float*)d_in[4];
    const float* wv    = (const float*)d_in[5];
    const float* wfc   = (const float*)d_in[6];
    const float* gamma = (const float*)d_in[7];
    const float* beta  = (const float*)d_in[8];

    float* outp = (float*)d_out;            // [B,L,1,D]
    float* pooledp = outp + 2097152;        // [B,H,L,L]

    cudaFuncSetAttribute(k_eld_mma, cudaFuncAttributeMaxDynamicSharedMemorySize, ELD_SMEM);

    k_init<<<128, 256>>>();
    k_proj<<<dim3(8, 64, 3), 256>>>(q, k, v, wq, wk, wv);
    k_eld_mma<<<dim3(16, 16, 16), 256, ELD_SMEM>>>();
    k_row2<<<32768, 256>>>(pooledp);
    k_fc<<<dim3(8, 64), 256>>>(wfc);
    k_ln<<<4096, 128>>>(q, gamma, beta, outp);
}

// round 5
// speedup vs baseline: 1.8398x; 1.4683x over previous
#include <cuda_runtime.h>
#include <cuda_bf16.h>
#include <math.h>

// B=2, L=2048, H=8, DK=DV=64, D=512, KSZ=3, pad=1
#define NROWS 32768            // B*H*L
#define BH    16               // B*H
#define LSEQ  2048
#define DHEAD 64
#define DMOD  512
#define M4    4096             // B*L

// ---------------- device scratch -------------------------------------------
__device__ float g_vh[BH * LSEQ * DHEAD];
__device__ __align__(128) __nv_bfloat16 g_qs[3][BH * LSEQ * DHEAD];   // bf16x3 splits of qh
__device__ __align__(128) __nv_bfloat16 g_ks[3][BH * LSEQ * DHEAD];   // bf16x3 splits of kh
__device__ float g_eld[(size_t)BH * LSEQ * LSEQ];   // 268MB logits
__device__ float g_attnout[M4 * DMOD];
__device__ float g_fcout[M4 * DMOD];
__device__ float g_dtab[4095];
__device__ unsigned int g_rowmax_u[NROWS];

// ---------------- helpers ----------------------------------------------------
__device__ __forceinline__ unsigned smem_u32(const void* p) {
    unsigned a;
    asm("{ .reg .u64 t; cvta.to.shared.u64 t, %1; cvt.u32.u64 %0, t; }" : "=r"(a) : "l"(p));
    return a;
}
__device__ __forceinline__ unsigned sw128(unsigned x) { return x ^ ((x >> 3) & 0x70); }

#define LDSM_X4(r0, r1, r2, r3, addr) \
    asm volatile("ldmatrix.sync.aligned.m8n8.x4.shared.b16 {%0,%1,%2,%3}, [%4];" \
                 : "=r"(r0), "=r"(r1), "=r"(r2), "=r"(r3) : "r"(addr))

#define MMA16816(d, a, b) \
    asm volatile("mma.sync.aligned.m16n8k16.row.col.f32.bf16.bf16.f32 " \
                 "{%0,%1,%2,%3}, {%4,%5,%6,%7}, {%8,%9}, {%0,%1,%2,%3};" \
                 : "+f"((d)[0]), "+f"((d)[1]), "+f"((d)[2]), "+f"((d)[3]) \
                 : "r"((a)[0]), "r"((a)[1]), "r"((a)[2]), "r"((a)[3]), \
                   "r"((b)[0]), "r"((b)[1]))

extern __shared__ char dsmem[];

// ---------------- shared HMMA inner machinery --------------------------------
// One K=64 chunk: A splits at sbA + s*16384, B splits at sbB + s*16384.
// Fires split products with a + s <= NS-1 (6 products for NS=3, 3 for NS=2).
template <int NS>
__device__ __forceinline__ void mma_chunk(unsigned sbA, unsigned sbB,
                                          int wr, int wc, int sub, int l7,
                                          float acc[2][8][4]) {
#pragma unroll
    for (int ks = 0; ks < 4; ks++) {
        int kb = ks * 32;
        unsigned afr[NS][2][4];
#pragma unroll
        for (int s = 0; s < NS; s++)
#pragma unroll
            for (int mi = 0; mi < 2; mi++) {
                int r = wr * 32 + mi * 16 + l7 + (sub & 1) * 8;
                int byt = kb + (sub >> 1) * 16;
                unsigned ad = sbA + s * 16384 + sw128((unsigned)(r * 128 + byt));
                LDSM_X4(afr[s][mi][0], afr[s][mi][1], afr[s][mi][2], afr[s][mi][3], ad);
            }
#pragma unroll
        for (int s = 0; s < NS; s++) {
            unsigned bfr[8][2];
#pragma unroll
            for (int np = 0; np < 4; np++) {
                int n = wc * 64 + np * 16 + l7 + (sub >> 1) * 8;
                int byt = kb + (sub & 1) * 16;
                unsigned bd = sbB + s * 16384 + sw128((unsigned)(n * 128 + byt));
                unsigned r0, r1, r2, r3;
                LDSM_X4(r0, r1, r2, r3, bd);
                bfr[np * 2][0] = r0; bfr[np * 2][1] = r1;
                bfr[np * 2 + 1][0] = r2; bfr[np * 2 + 1][1] = r3;
            }
#pragma unroll
            for (int a = 0; a < NS - s; a++)
#pragma unroll
                for (int mi = 0; mi < 2; mi++)
#pragma unroll
                    for (int ni = 0; ni < 8; ni++)
                        MMA16816(acc[mi][ni], afr[a][mi], bfr[ni]);
        }
    }
}

// Load a 128x64 fp32 tile, split in-register into NS bf16 tiles (SW128 smem).
template <int NS>
__device__ __forceinline__ void load_split_tile(const float* __restrict__ src,
                                                int row0, int kc, char* dst) {
    int tid = threadIdx.x;
#pragma unroll
    for (int p = 0; p < 8; p++) {
        int f = tid + p * 256;
        int r = f >> 4;
        int c4 = (f & 15) << 2;
        float4 v = *(const float4*)(src + (size_t)(row0 + r) * 512 + kc + c4);
        float xs[4] = {v.x, v.y, v.z, v.w};
        union { __nv_bfloat16 h[4]; uint2 u; } pk[NS];
#pragma unroll
        for (int u = 0; u < 4; u++) {
            float x = xs[u];
#pragma unroll
            for (int s = 0; s < NS; s++) {
                __nv_bfloat16 b = __float2bfloat16(x);
                pk[s].h[u] = b;
                x -= __bfloat162float(b);
            }
        }
        unsigned off = sw128((unsigned)(r * 128 + c4 * 2));
#pragma unroll
        for (int s = 0; s < NS; s++)
            *(uint2*)(dst + s * 16384 + off) = pk[s].u;
    }
}

// Full 128x128 GEMM: C = A[m0..+127, 0..511] . W[n0..+127, 0..511]^T
template <int NS>
__device__ __forceinline__ void gemm_core(const float* A, const float* W,
                                          unsigned sb, char* smp,
                                          float acc[2][8][4]) {
    int tid = threadIdx.x;
    int wid = tid >> 5, lane = tid & 31;
    int m0 = blockIdx.y * 128, n0 = blockIdx.x * 128;
#pragma unroll 1
    for (int kc = 0; kc < 512; kc += 64) {
        __syncthreads();
        load_split_tile<NS>(A, m0, kc, smp);
        load_split_tile<NS>(W, n0, kc, smp + NS * 16384);
        __syncthreads();
        mma_chunk<NS>(sb, sb + NS * 16384, wid & 3, wid >> 2, lane >> 3, lane & 7, acc);
    }
}

__device__ __forceinline__ void stage_acc(float* stage, float acc[2][8][4],
                                          int wid, int lane) {
    int rbase = (wid & 3) * 32 + (lane >> 2);
    int cbase = (wid >> 2) * 64 + (lane & 3) * 2;
#pragma unroll
    for (int mi = 0; mi < 2; mi++)
#pragma unroll
        for (int ni = 0; ni < 8; ni++)
#pragma unroll
            for (int u = 0; u < 4; u++)
                stage[(rbase + mi * 16 + (u >> 1) * 8) * 132 +
                      cbase + ni * 8 + (u & 1)] = acc[mi][ni][u];
}

// ---------------- init ------------------------------------------------------
__global__ void k_init() {
    int t = blockIdx.x * blockDim.x + threadIdx.x;
    if (t < 4095) {
        double alpha = -log(0.001 / 7.0 * 3.0);   // ALPHA_C
        g_dtab[t] = (float)(-alpha * (double)(t - 2047));
    }
    if (t < NROWS) g_rowmax_u[t] = 0u;
}

// ---------------- q/k projection (bf16x3, 6 products) -----------------------
__global__ void __launch_bounds__(256, 2) k_projqk(const float* __restrict__ qi,
                                                   const float* __restrict__ ki,
                                                   const float* __restrict__ wq,
                                                   const float* __restrict__ wk) {
    int z = blockIdx.z;
    const float* A = z ? ki : qi;
    const float* W = z ? wk : wq;
    int tid = threadIdx.x;
    int wid = tid >> 5, lane = tid & 31;

    unsigned raw = smem_u32(dsmem);
    unsigned sb = (raw + 1023) & ~1023u;
    char* smp = dsmem + (sb - raw);

    float acc[2][8][4];
#pragma unroll
    for (int mi = 0; mi < 2; mi++)
#pragma unroll
        for (int ni = 0; ni < 8; ni++)
#pragma unroll
            for (int u = 0; u < 4; u++) acc[mi][ni][u] = 0.f;

    gemm_core<3>(A, W, sb, smp, acc);

    __syncthreads();
    float* stage = (float*)smp;
    stage_acc(stage, acc, wid, lane);
    __syncthreads();

    __nv_bfloat16* S0 = z ? g_ks[0] : g_qs[0];
    __nv_bfloat16* S1 = z ? g_ks[1] : g_qs[1];
    __nv_bfloat16* S2 = z ? g_ks[2] : g_qs[2];
    int m0 = blockIdx.y * 128, n0 = blockIdx.x * 128;
#pragma unroll
    for (int p = 0; p < 16; p++) {
        int f = tid + p * 256;
        int r = f >> 5, q = f & 31;
        int m = m0 + r, bb = m >> 11, l = m & 2047;
        int n = n0 + q * 4, h = n >> 6, dk = n & 63;
        float4 v = *(const float4*)(stage + r * 132 + q * 4);
        float xs[4] = {v.x, v.y, v.z, v.w};
        union { __nv_bfloat16 h4[4]; uint2 u; } p0, p1, p2;
#pragma unroll
        for (int u = 0; u < 4; u++) {
            float x = xs[u];
            __nv_bfloat16 b0 = __float2bfloat16(x);
            float r1 = x - __bfloat162float(b0);
            __nv_bfloat16 b1 = __float2bfloat16(r1);
            float r2 = r1 - __bfloat162float(b1);
            __nv_bfloat16 b2 = __float2bfloat16(r2);
            p0.h4[u] = b0; p1.h4[u] = b1; p2.h4[u] = b2;
        }
        size_t off = ((size_t)(bb * 8 + h) * LSEQ + l) * 64 + dk;
        *(uint2*)(S0 + off) = p0.u;
        *(uint2*)(S1 + off) = p1.u;
        *(uint2*)(S2 + off) = p2.u;
    }
}

// ---------------- v projection (bf16x2, 3 products) -------------------------
__global__ void __launch_bounds__(256, 2) k_projv(const float* __restrict__ vi,
                                                  const float* __restrict__ wv) {
    int tid = threadIdx.x;
    int wid = tid >> 5, lane = tid & 31;
    unsigned raw = smem_u32(dsmem);
    unsigned sb = (raw + 1023) & ~1023u;
    char* smp = dsmem + (sb - raw);

    float acc[2][8][4];
#pragma unroll
    for (int mi = 0; mi < 2; mi++)
#pragma unroll
        for (int ni = 0; ni < 8; ni++)
#pragma unroll
            for (int u = 0; u < 4; u++) acc[mi][ni][u] = 0.f;

    gemm_core<2>(vi, wv, sb, smp, acc);

    __syncthreads();
    float* stage = (float*)smp;
    stage_acc(stage, acc, wid, lane);
    __syncthreads();

    int m0 = blockIdx.y * 128, n0 = blockIdx.x * 128;
#pragma unroll
    for (int p = 0; p < 16; p++) {
        int f = tid + p * 256;
        int r = f >> 5, q = f & 31;
        int m = m0 + r, bb = m >> 11, l = m & 2047;
        int n = n0 + q * 4, h = n >> 6, dk = n & 63;
        float4 v = *(const float4*)(stage + r * 132 + q * 4);
        *(float4*)(g_vh + ((size_t)(bb * 8 + h) * LSEQ + l) * 64 + dk) = v;
    }
}

// ---------------- fc projection (bf16x2, 3 products) ------------------------
__global__ void __launch_bounds__(256, 2) k_fc2(const float* __restrict__ wfc) {
    int tid = threadIdx.x;
    int wid = tid >> 5, lane = tid & 31;
    unsigned raw = smem_u32(dsmem);
    unsigned sb = (raw + 1023) & ~1023u;
    char* smp = dsmem + (sb - raw);

    float acc[2][8][4];
#pragma unroll
    for (int mi = 0; mi < 2; mi++)
#pragma unroll
        for (int ni = 0; ni < 8; ni++)
#pragma unroll
            for (int u = 0; u < 4; u++) acc[mi][ni][u] = 0.f;

    gemm_core<2>(g_attnout, wfc, sb, smp, acc);

    __syncthreads();
    float* stage = (float*)smp;
    stage_acc(stage, acc, wid, lane);
    __syncthreads();

    int m0 = blockIdx.y * 128, n0 = blockIdx.x * 128;
#pragma unroll
    for (int p = 0; p < 16; p++) {
        int f = tid + p * 256;
        int r = f >> 5, q = f & 31;
        float4 v = *(const float4*)(stage + r * 132 + q * 4);
        *(float4*)(g_fcout + (size_t)(m0 + r) * 512 + n0 + q * 4) = v;
    }
}

// ---------------- eld logits: HMMA bf16x3, reuse-optimized -------------------
__global__ void __launch_bounds__(256, 2) k_eld_mma() {
    int tid = threadIdx.x;
    int wid = tid >> 5, lane = tid & 31;
    int bh = blockIdx.z;
    int i0 = blockIdx.y * 128, j0 = blockIdx.x * 128;

    unsigned raw = smem_u32(dsmem);
    unsigned sb = (raw + 1023) & ~1023u;
    char* smp = dsmem + (sb - raw);

    size_t rbq = ((size_t)bh * LSEQ + i0) * 64;
    size_t rbk = ((size_t)bh * LSEQ + j0) * 64;
#pragma unroll
    for (int s = 0; s < 3; s++) {
        const char* qsrc = (const char*)(g_qs[s] + rbq);
        const char* ksrc = (const char*)(g_ks[s] + rbk);
#pragma unroll
        for (int p = 0; p < 4; p++) {
            int f = tid + p * 256;
            int r = f >> 3;
            int cb = (f & 7) * 16;
            unsigned off = sw128(r * 128 + cb);
            *(uint4*)(smp + s * 16384 + off) = *(const uint4*)(qsrc + r * 128 + cb);
            *(uint4*)(smp + 49152 + s * 16384 + off) = *(const uint4*)(ksrc + r * 128 + cb);
        }
    }
    __syncthreads();

    float acc[2][8][4];
#pragma unroll
    for (int mi = 0; mi < 2; mi++)
#pragma unroll
        for (int ni = 0; ni < 8; ni++)
#pragma unroll
            for (int u = 0; u < 4; u++) acc[mi][ni][u] = 0.f;

    mma_chunk<3>(sb, sb + 49152, wid & 3, wid >> 2, lane >> 3, lane & 7, acc);
    __syncthreads();

    // epilogue: transform + stage + rowmax
    float* stage = (float*)smp;
    int rbase = (wid & 3) * 32 + (lane >> 2);
    int cbase = (wid >> 2) * 64 + (lane & 3) * 2;
    float mx[2][2] = {{-INFINITY, -INFINITY}, {-INFINITY, -INFINITY}};
#pragma unroll
    for (int mi = 0; mi < 2; mi++) {
#pragma unroll
        for (int ni = 0; ni < 8; ni++) {
#pragma unroll
            for (int u = 0; u < 4; u++) {
                int rloc = rbase + mi * 16 + (u >> 1) * 8;
                int cloc = cbase + ni * 8 + (u & 1);
                int i = i0 + rloc, j = j0 + cloc;
                float e = g_dtab[j - i + 2047] * (acc[mi][ni][u] * 0.125f);
                stage[rloc * 132 + cloc] = e;
                mx[mi][u >> 1] = fmaxf(mx[mi][u >> 1], e);
            }
        }
    }
#pragma unroll
    for (int mi = 0; mi < 2; mi++)
#pragma unroll
        for (int hh = 0; hh < 2; hh++) {
            float r = mx[mi][hh];
            r = fmaxf(r, __shfl_xor_sync(0xffffffffu, r, 1));
            r = fmaxf(r, __shfl_xor_sync(0xffffffffu, r, 2));
            if ((lane & 3) == 0) {
                int i = i0 + rbase + mi * 16 + hh * 8;
                unsigned u = __float_as_uint(r);
                unsigned key = (u & 0x80000000u) ? ~u : (u | 0x80000000u);
                atomicMax(&g_rowmax_u[bh * LSEQ + i], key);
            }
        }
    __syncthreads();

    float* erow = g_eld + ((size_t)bh * LSEQ + i0) * LSEQ + j0;
#pragma unroll
    for (int p = 0; p < 16; p++) {
        int f = tid + p * 256;
        int r = f >> 5, q = f & 31;
        float4 v = *(const float4*)(stage + r * 132 + q * 4);
        *(float4*)(erow + (size_t)r * LSEQ + q * 4) = v;
    }
}

// ---------------- sparse softmax + pool + PV --------------------------------
__global__ void k_row2(float* __restrict__ pooled_out) {
    __shared__ __align__(16) float p_sh[2048];
    __shared__ unsigned int mask_sh[64];
    __shared__ float redS[8];

    int tid = threadIdx.x;
    int row = blockIdx.x;
    int bh = row >> 11;
    int i  = row & 2047;
    int b  = bh >> 3, h = bh & 7;

    ((float4*)p_sh)[tid * 2]     = make_float4(0.f, 0.f, 0.f, 0.f);
    ((float4*)p_sh)[tid * 2 + 1] = make_float4(0.f, 0.f, 0.f, 0.f);
    if (tid < 64) mask_sh[tid] = 0u;

    unsigned int kk = g_rowmax_u[row];
    unsigned int ub = (kk & 0x80000000u) ? (kk ^ 0x80000000u) : ~kk;
    float mx = __uint_as_float(ub);

    const float* eldrow = g_eld + (size_t)row * LSEQ;
    int j0 = tid * 8;
    float4 v0 = *(const float4*)(eldrow + j0);
    float4 v1 = *(const float4*)(eldrow + j0 + 4);
    float e8[8] = {v0.x, v0.y, v0.z, v0.w, v1.x, v1.y, v1.z, v1.w};

    float ev[8];
    float lsum = 0.f;
#pragma unroll
    for (int u = 0; u < 8; u++) {
        float arg = e8[u] - mx;
        float e = 0.f;
        if (arg > -88.0f) e = expf(arg);
        ev[u] = e;
        lsum += e;
    }
#pragma unroll
    for (int o = 16; o > 0; o >>= 1)
        lsum += __shfl_xor_sync(0xffffffffu, lsum, o);
    if ((tid & 31) == 0) redS[tid >> 5] = lsum;
    __syncthreads();
    float S = ((redS[0] + redS[1]) + (redS[2] + redS[3])) +
              ((redS[4] + redS[5]) + (redS[6] + redS[7]));

    unsigned int bits = 0;
#pragma unroll
    for (int u = 0; u < 8; u++) {
        if (ev[u] != 0.f) { p_sh[j0 + u] = ev[u] / S; bits |= (1u << u); }
    }
    if (bits) {
#pragma unroll
        for (int u = 0; u < 8; u++) {
            if (bits & (1u << u)) {
                int jj = j0 + u;
                int lo = (jj > 0) ? jj - 1 : 0;
                int hi = (jj < 2047) ? jj + 1 : 2047;
                for (int pp = lo; pp <= hi; pp++)
                    atomicOr(&mask_sh[pp >> 5], 1u << (pp & 31));
            }
        }
    }
    __syncthreads();

    unsigned int wmask = mask_sh[tid >> 2];
    unsigned int myb = (wmask >> ((tid & 3) * 8)) & 0xffu;
    float pv[8] = {0.f, 0.f, 0.f, 0.f, 0.f, 0.f, 0.f, 0.f};
    if (myb) {
#pragma unroll
        for (int u = 0; u < 8; u++) {
            if (myb & (1u << u)) {
                int pos = j0 + u;
                float pm = (pos > 0)    ? p_sh[pos - 1] : 0.f;
                float pz = p_sh[pos];
                float pq = (pos < 2047) ? p_sh[pos + 1] : 0.f;
                pv[u] = ((pm + pz) + pq) / 3.0f;
            }
        }
    }
    size_t prow = (size_t)row * LSEQ + j0;
    *(float4*)(pooled_out + prow)     = make_float4(pv[0], pv[1], pv[2], pv[3]);
    *(float4*)(pooled_out + prow + 4) = make_float4(pv[4], pv[5], pv[6], pv[7]);

    if (tid < 64) {
        const float* vbase = g_vh + (size_t)bh * LSEQ * 64 + tid;
        float acc = 0.f;
#pragma unroll 1
        for (int w = 0; w < 64; w++) {
            unsigned int bw = mask_sh[w];
            while (bw) {
                int bp = __ffs((int)bw) - 1;
                bw &= (bw - 1);
                int pos = w * 32 + bp;
                float pm = (pos > 0)    ? p_sh[pos - 1] : 0.f;
                float pz = p_sh[pos];
                float pq = (pos < 2047) ? p_sh[pos + 1] : 0.f;
                float val = ((pm + pz) + pq) / 3.0f;
                acc = fmaf(val, vbase[(size_t)pos * 64], acc);
            }
        }
        g_attnout[((size_t)(b * LSEQ + i)) * DMOD + h * 64 + tid] = acc;
    }
}

// ---------------- residual + LayerNorm --------------------------------------
__global__ void k_ln(const float* __restrict__ resid, const float* __restrict__ gamma,
                     const float* __restrict__ beta, float* __restrict__ outp) {
    __shared__ float red[128];
    int m = blockIdx.x;
    int tid = threadIdx.x;
    float4 f = *(const float4*)(g_fcout + (size_t)m * 512 + tid * 4);
    float4 r = *(const float4*)(resid + (size_t)m * 512 + tid * 4);
    float y[4] = {f.x + r.x, f.y + r.y, f.z + r.z, f.w + r.w};

    float s = (y[0] + y[1]) + (y[2] + y[3]);
    red[tid] = s;
    __syncthreads();
    for (int st = 64; st > 0; st >>= 1) {
        if (tid < st) red[tid] += red[tid + st];
        __syncthreads();
    }
    float mu = red[0] * (1.0f / 512.0f);
    __syncthreads();

    float d[4] = {y[0] - mu, y[1] - mu, y[2] - mu, y[3] - mu};
    float sq = (d[0] * d[0] + d[1] * d[1]) + (d[2] * d[2] + d[3] * d[3]);
    red[tid] = sq;
    __syncthreads();
    for (int st = 64; st > 0; st >>= 1) {
        if (tid < st) red[tid] += red[tid + st];
        __syncthreads();
    }
    float var = red[0] * (1.0f / 512.0f);
    float inv = 1.0f / sqrtf(var + 1e-6f);

    float4 g = *(const float4*)(gamma + tid * 4);
    float4 bb = *(const float4*)(beta + tid * 4);
    float4 o = make_float4(d[0] * inv * g.x + bb.x, d[1] * inv * g.y + bb.y,
                           d[2] * inv * g.z + bb.z, d[3] * inv * g.w + bb.w);
    *(float4*)(outp + (size_t)m * 512 + tid * 4) = o;
}

// ---------------- launch -----------------------------------------------------
#define SMEM3 (98304 + 1024)      // 6 x 16KB tiles (also covers 67.5KB stage)
#define SMEM2 (67584 + 1024)      // 4 x 16KB tiles, stage needs 67.5KB

extern "C" void kernel_launch(void* const* d_in, const int* in_sizes, int n_in,
                              void* d_out, int out_size) {
    const float* q     = (const float*)d_in[0];
    const float* k     = (const float*)d_in[1];
    const float* v     = (const float*)d_in[2];
    const float* wq    = (const float*)d_in[3];
    const float* wk    = (const float*)d_in[4];
    const float* wv    = (const float*)d_in[5];
    const float* wfc   = (const float*)d_in[6];
    const float* gamma = (const float*)d_in[7];
    const float* beta  = (const float*)d_in[8];

    float* outp = (float*)d_out;            // [B,L,1,D]
    float* pooledp = outp + 2097152;        // [B,H,L,L]

    cudaFuncSetAttribute(k_projqk, cudaFuncAttributeMaxDynamicSharedMemorySize, SMEM3);
    cudaFuncSetAttribute(k_projv,  cudaFuncAttributeMaxDynamicSharedMemorySize, SMEM2);
    cudaFuncSetAttribute(k_fc2,    cudaFuncAttributeMaxDynamicSharedMemorySize, SMEM2);
    cudaFuncSetAttribute(k_eld_mma, cudaFuncAttributeMaxDynamicSharedMemorySize, SMEM3);

    k_init<<<128, 256>>>();
    k_projqk<<<dim3(4, 32, 2), 256, SMEM3>>>(q, k, wq, wk);
    k_projv<<<dim3(4, 32), 256, SMEM2>>>(v, wv);
    k_eld_mma<<<dim3(16, 16, 16), 256, SMEM3>>>();
    k_row2<<<32768, 256>>>(pooledp);
    k_fc2<<<dim3(4, 32), 256, SMEM2>>>(wfc);
    k_ln<<<4096, 128>>>(q, gamma, beta, outp);
}